// round 5
// baseline (speedup 1.0000x reference)
#include <cuda_runtime.h>
#include <math.h>
#include <stdint.h>

#define NH   4
#define NN   4096
#define DIN  256
#define DOUT 128
#define MT   64       // i-rows per CTA
#define JT   64       // j-tile
#define WP   68       // wT row pad (floats), 16B-aligned stride

// scratch (allocation-free rule: __device__ globals)
__device__ float  g_h[NH * NN * DOUT];     // h = x @ W   (8 MB)
__device__ float4 g_idat[NH * NN];         // (s_i, exp(s_i), exp(0.2 s_i), 0)
__device__ float4 g_jdat[NH * NN];         // (s_j, exp(s_j), exp(0.2 s_j), 0)

typedef unsigned long long ull;

__device__ __forceinline__ ull pack2(float x, float y) {
    ull r; asm("mov.b64 %0, {%1, %2};" : "=l"(r) : "f"(x), "f"(y)); return r;
}
__device__ __forceinline__ void fma2(ull& d, ull a, ull b) {
    asm("fma.rn.f32x2 %0, %1, %2, %0;" : "+l"(d) : "l"(a), "l"(b));
}
__device__ __forceinline__ float2 unpack2(ull v) {
    float lo, hi; asm("mov.b64 {%0, %1}, %2;" : "=f"(lo), "=f"(hi) : "l"(v));
    float2 r; r.x = lo; r.y = hi; return r;
}

// ---------------------------------------------------------------------------
// K1: h[hd][n][o] = sum_d x[n][d] * W[hd][d][o]
// grid (64, 4), 256 threads; 64-row x 128-col tile per CTA
// ---------------------------------------------------------------------------
__global__ __launch_bounds__(256) void k1_gemm_h(const float* __restrict__ x,
                                                 const float* __restrict__ W) {
    __shared__ float xsT[32][68];     // transposed x tile [k][r]
    __shared__ float ws[32][128];     // W tile [k][o]
    const int hd = blockIdx.y;
    const int n0 = blockIdx.x * 64;
    const int tid = threadIdx.x;
    const int tx = tid & 15, ty = tid >> 4;
    const float* Wh = W + (size_t)hd * DIN * DOUT;

    ull acc[4][4];
#pragma unroll
    for (int r = 0; r < 4; r++)
#pragma unroll
        for (int c = 0; c < 4; c++) acc[r][c] = 0ull;

    for (int kk = 0; kk < DIN; kk += 32) {
        __syncthreads();
        // load x tile transposed: 64 rows x 32 cols
#pragma unroll
        for (int it = 0; it < 2; it++) {
            int l = tid + it * 256;           // 0..511
            int r = l >> 3, cg = l & 7;
            float4 v = *(const float4*)(x + (size_t)(n0 + r) * DIN + kk + cg * 4);
            xsT[cg * 4 + 0][r] = v.x; xsT[cg * 4 + 1][r] = v.y;
            xsT[cg * 4 + 2][r] = v.z; xsT[cg * 4 + 3][r] = v.w;
        }
        // load W tile: 32 x 128 contiguous
#pragma unroll
        for (int it = 0; it < 4; it++) {
            int l = tid + it * 256;           // 0..1023 float4
            ((float4*)&ws[0][0])[l] = *(const float4*)(Wh + (size_t)kk * DOUT + l * 4);
        }
        __syncthreads();
#pragma unroll 8
        for (int k = 0; k < 32; k++) {
            float4 av = *(float4*)&xsT[k][ty * 4];
            float4 b0 = *(float4*)&ws[k][tx * 4];
            float4 b1 = *(float4*)&ws[k][64 + tx * 4];
            ull bb0 = pack2(b0.x, b0.y), bb1 = pack2(b0.z, b0.w);
            ull bb2 = pack2(b1.x, b1.y), bb3 = pack2(b1.z, b1.w);
            float ar[4] = {av.x, av.y, av.z, av.w};
#pragma unroll
            for (int r = 0; r < 4; r++) {
                ull arr = pack2(ar[r], ar[r]);
                fma2(acc[r][0], arr, bb0); fma2(acc[r][1], arr, bb1);
                fma2(acc[r][2], arr, bb2); fma2(acc[r][3], arr, bb3);
            }
        }
    }
#pragma unroll
    for (int r = 0; r < 4; r++) {
        float* dst = g_h + ((size_t)hd * NN + n0 + ty * 4 + r) * DOUT;
        float2 p0 = unpack2(acc[r][0]), p1 = unpack2(acc[r][1]);
        float2 p2 = unpack2(acc[r][2]), p3 = unpack2(acc[r][3]);
        *(float4*)(dst + tx * 4)      = make_float4(p0.x, p0.y, p1.x, p1.y);
        *(float4*)(dst + 64 + tx * 4) = make_float4(p2.x, p2.y, p3.x, p3.y);
    }
}

// ---------------------------------------------------------------------------
// K2: per (head,row): s_i = h . a1, s_j = h . a2, plus exp factorizations
// one warp per row; grid 2048 x 256
// ---------------------------------------------------------------------------
__global__ __launch_bounds__(256) void k2_sef(const float* __restrict__ a) {
    const int warp = threadIdx.x >> 5, lane = threadIdx.x & 31;
    const int ridx = blockIdx.x * 8 + warp;        // hd*NN + n
    const int hd = ridx >> 12;
    const float* hrow = g_h + (size_t)ridx * DOUT;
    const float* ah = a + hd * 256;
    float s1 = 0.f, s2 = 0.f;
#pragma unroll
    for (int c = lane; c < DOUT; c += 32) {
        float hv = hrow[c];
        s1 += hv * ah[c];
        s2 += hv * ah[DOUT + c];
    }
#pragma unroll
    for (int o = 16; o > 0; o >>= 1) {
        s1 += __shfl_xor_sync(0xffffffffu, s1, o);
        s2 += __shfl_xor_sync(0xffffffffu, s2, o);
    }
    if (lane == 0) {
        g_idat[ridx] = make_float4(s1, expf(s1), expf(0.2f * s1), 0.f);
        g_jdat[ridx] = make_float4(s2, expf(s2), expf(0.2f * s2), 0.f);
    }
}

// ---------------------------------------------------------------------------
// K3: fused masked-softmax-weighted aggregation.
//   w_ij = mask_ij * ( (s_i+s_j >= 0) ? E_i*E_j : F_i*F_j )
//   out[i, hd*128+o] = (sum_j w_ij h[j][o]) / (sum_j w_ij)
// grid (64, 4), 256 threads, 52KB dynamic smem, occupancy 2
// ---------------------------------------------------------------------------
extern __shared__ float k3smem[];
__global__ __launch_bounds__(256, 2) void k3_main(const int* __restrict__ A,
                                                  float* __restrict__ out) {
    float* hs   = k3smem;                 // [64][128]    8192 floats
    float* wT   = hs + JT * DOUT;         // [64][WP]     4352 floats (wT[j][i])
    float* sSi  = wT + JT * WP;           // 64
    float* sEi  = sSi + MT;               // 64
    float* sFi  = sEi + MT;               // 64
    float* zred = sFi + MT;               // 256
    float* zinv = zred + 256;             // 64

    const int hd = blockIdx.y;
    const int i0 = blockIdx.x * MT;
    const int tid = threadIdx.x;
    const int tx = tid & 15, ty = tid >> 4;
    const int il = tid >> 2, jq = (tid & 3) << 4;

    if (tid < MT) {
        float4 v = g_idat[hd * NN + i0 + tid];
        sSi[tid] = v.x; sEi[tid] = v.y; sFi[tid] = v.z;
    }

    ull acc[4][4];
#pragma unroll
    for (int r = 0; r < 4; r++)
#pragma unroll
        for (int c = 0; c < 4; c++) acc[r][c] = 0ull;
    float zloc = 0.f;

    __syncthreads();

    for (int j0 = 0; j0 < NN; j0 += JT) {
        // ---- phase A: build w tile (64 j x 64 i) + Z partials
        {
            const int ig = i0 + il;
            const int4* Arow = (const int4*)(A + (size_t)ig * NN + j0 + jq);
            const float4* jd = g_jdat + hd * NN + j0 + jq;
            const float si = sSi[il], Ei = sEi[il], Fi = sFi[il];
            float z = 0.f;
#pragma unroll
            for (int m = 0; m < 4; m++) {
                int4 av = Arow[m];
                int a4[4] = {av.x, av.y, av.z, av.w};
#pragma unroll
                for (int q = 0; q < 4; q++) {
                    int jl = jq + m * 4 + q;
                    float4 jv = jd[m * 4 + q];
                    bool mk = (a4[q] > 0) || (j0 + jl == ig);
                    float t = si + jv.x;
                    float w = mk ? ((t >= 0.f) ? Ei * jv.y : Fi * jv.z) : 0.f;
                    wT[jl * WP + il] = w;
                    z += w;
                }
            }
            zloc += z;
        }
        // ---- phase B: stage h[j0:j0+64][0:128]
        {
            const float4* src = (const float4*)(g_h + ((size_t)hd * NN + j0) * DOUT);
            float4* dst = (float4*)hs;
#pragma unroll
            for (int it = 0; it < 8; it++) dst[tid + it * 256] = src[tid + it * 256];
        }
        __syncthreads();
        // ---- phase C: acc += w^T-tile x h-tile (f32x2 packed FMA)
#pragma unroll 8
        for (int k = 0; k < JT; k++) {
            float4 wv = *(float4*)&wT[k * WP + ty * 4];
            float4 h0 = *(float4*)&hs[k * DOUT + tx * 4];
            float4 h1 = *(float4*)&hs[k * DOUT + 64 + tx * 4];
            ull b0 = pack2(h0.x, h0.y), b1 = pack2(h0.z, h0.w);
            ull b2 = pack2(h1.x, h1.y), b3 = pack2(h1.z, h1.w);
            float wr[4] = {wv.x, wv.y, wv.z, wv.w};
#pragma unroll
            for (int r = 0; r < 4; r++) {
                ull ar = pack2(wr[r], wr[r]);
                fma2(acc[r][0], ar, b0); fma2(acc[r][1], ar, b1);
                fma2(acc[r][2], ar, b2); fma2(acc[r][3], ar, b3);
            }
        }
        __syncthreads();   // before next tile overwrites wT/hs
    }

    // ---- Z reduction (4 partials per row)
    zred[tid] = zloc;
    __syncthreads();
    if (tid < MT)
        zinv[tid] = 1.0f / (zred[tid * 4] + zred[tid * 4 + 1] +
                            zred[tid * 4 + 2] + zred[tid * 4 + 3]);
    __syncthreads();

    // ---- epilogue: normalize + write out[n][hd*128+o]
#pragma unroll
    for (int r = 0; r < 4; r++) {
        int ir = ty * 4 + r;
        float s = zinv[ir];
        float* dst = out + (size_t)(i0 + ir) * (NH * DOUT) + hd * DOUT;
        float2 p0 = unpack2(acc[r][0]), p1 = unpack2(acc[r][1]);
        float2 p2 = unpack2(acc[r][2]), p3 = unpack2(acc[r][3]);
        *(float4*)(dst + tx * 4)      = make_float4(p0.x * s, p0.y * s, p1.x * s, p1.y * s);
        *(float4*)(dst + 64 + tx * 4) = make_float4(p2.x * s, p2.y * s, p3.x * s, p3.y * s);
    }
}

// ---------------------------------------------------------------------------
extern "C" void kernel_launch(void* const* d_in, const int* in_sizes, int n_in,
                              void* d_out, int out_size) {
    const float* x = (const float*)d_in[0];   // (4096, 256) f32
    const int*   A = (const int*)d_in[1];     // (4096, 4096) i32
    const float* W = (const float*)d_in[2];   // (4, 256, 128) f32
    const float* a = (const float*)d_in[3];   // (4, 256, 1) f32
    float* out = (float*)d_out;               // (4096, 512) f32

    const int k3_smem = (JT * DOUT + JT * WP + 3 * MT + 256 + 64) * (int)sizeof(float);
    cudaFuncSetAttribute(k3_main, cudaFuncAttributeMaxDynamicSharedMemorySize, k3_smem);

    k1_gemm_h<<<dim3(NN / 64, NH), 256>>>(x, W);
    k2_sef<<<(NH * NN) / 8, 256>>>(a);
    k3_main<<<dim3(NN / MT, NH), 256, k3_smem>>>(A, out);
}

// round 9
// speedup vs baseline: 1.4835x; 1.4835x over previous
#include <cuda_runtime.h>
#include <cuda_bf16.h>
#include <math.h>
#include <stdint.h>

#define NH   4
#define NN   4096
#define DIN  256
#define DOUT 128
#define JT   32          // j-tile for k3
#define RS   80          // smem row stride bytes (40 bf16), bank-conflict-free ldmatrix

// ---------------- device scratch (no allocations allowed) -------------------
__device__ float          g_h[NH * NN * DOUT];       // h fp32 [hd][n][o]  (8MB)
__device__ __nv_bfloat16  g_hThi[NH * DOUT * NN];    // h^T hi [hd][o][n]  (4MB)
__device__ __nv_bfloat16  g_hTlo[NH * DOUT * NN];    // h^T lo             (4MB)
__device__ float4         g_idat[NH * NN];           // (s_i, e^{s_i}, e^{.2 s_i}, 0)
__device__ float4         g_jdat[NH * NN];           // (s_j, e^{s_j}, e^{.2 s_j}, 0)

typedef unsigned long long ull;

__device__ __forceinline__ uint32_t smem_u32(const void* p) {
    uint32_t a;
    asm("{ .reg .u64 t; cvta.to.shared.u64 t, %1; cvt.u32.u64 %0, t; }" : "=r"(a) : "l"(p));
    return a;
}
__device__ __forceinline__ ull pack2(float x, float y) {
    ull r; asm("mov.b64 %0, {%1, %2};" : "=l"(r) : "f"(x), "f"(y)); return r;
}
__device__ __forceinline__ void fma2(ull& d, ull a, ull b) {
    asm("fma.rn.f32x2 %0, %1, %2, %0;" : "+l"(d) : "l"(a), "l"(b));
}
__device__ __forceinline__ float2 unpack2(ull v) {
    float lo, hi; asm("mov.b64 {%0, %1}, %2;" : "=f"(lo), "=f"(hi) : "l"(v));
    float2 r; r.x = lo; r.y = hi; return r;
}
__device__ __forceinline__ void ldsm4(uint32_t* r, uint32_t addr) {
    asm volatile("ldmatrix.sync.aligned.m8n8.x4.shared.b16 {%0,%1,%2,%3}, [%4];"
                 : "=r"(r[0]), "=r"(r[1]), "=r"(r[2]), "=r"(r[3]) : "r"(addr));
}
__device__ __forceinline__ void mma_bf16(float* d, const uint32_t* a, uint32_t b0, uint32_t b1) {
    asm volatile(
        "mma.sync.aligned.m16n8k16.row.col.f32.bf16.bf16.f32 "
        "{%0,%1,%2,%3}, {%4,%5,%6,%7}, {%8,%9}, {%0,%1,%2,%3};"
        : "+f"(d[0]), "+f"(d[1]), "+f"(d[2]), "+f"(d[3])
        : "r"(a[0]), "r"(a[1]), "r"(a[2]), "r"(a[3]), "r"(b0), "r"(b1));
}
__device__ __forceinline__ uint32_t bf16x2_split_hi(float f0, float f1, uint32_t& lo_out) {
    __nv_bfloat16 b0 = __float2bfloat16(f0), b1 = __float2bfloat16(f1);
    uint32_t hp = ((uint32_t)__bfloat16_as_ushort(b1) << 16) | __bfloat16_as_ushort(b0);
    float r0 = f0 - __bfloat162float(b0), r1 = f1 - __bfloat162float(b1);
    __nv_bfloat16 c0 = __float2bfloat16(r0), c1 = __float2bfloat16(r1);
    lo_out = ((uint32_t)__bfloat16_as_ushort(c1) << 16) | __bfloat16_as_ushort(c0);
    return hp;
}

// ---------------------------------------------------------------------------
// K1: h = x @ W   (measured 33us)
// ---------------------------------------------------------------------------
__global__ __launch_bounds__(256) void k1_gemm_h(const float* __restrict__ x,
                                                 const float* __restrict__ W) {
    __shared__ float xsT[32][68];
    __shared__ float ws[32][128];
    const int hd = blockIdx.y;
    const int n0 = blockIdx.x * 64;
    const int tid = threadIdx.x;
    const int tx = tid & 15, ty = tid >> 4;
    const float* Wh = W + (size_t)hd * DIN * DOUT;

    ull acc[4][4];
#pragma unroll
    for (int r = 0; r < 4; r++)
#pragma unroll
        for (int c = 0; c < 4; c++) acc[r][c] = 0ull;

    for (int kk = 0; kk < DIN; kk += 32) {
        __syncthreads();
#pragma unroll
        for (int it = 0; it < 2; it++) {
            int l = tid + it * 256;
            int r = l >> 3, cg = l & 7;
            float4 v = *(const float4*)(x + (size_t)(n0 + r) * DIN + kk + cg * 4);
            xsT[cg * 4 + 0][r] = v.x; xsT[cg * 4 + 1][r] = v.y;
            xsT[cg * 4 + 2][r] = v.z; xsT[cg * 4 + 3][r] = v.w;
        }
#pragma unroll
        for (int it = 0; it < 4; it++) {
            int l = tid + it * 256;
            ((float4*)&ws[0][0])[l] = *(const float4*)(Wh + (size_t)kk * DOUT + l * 4);
        }
        __syncthreads();
#pragma unroll 8
        for (int k = 0; k < 32; k++) {
            float4 av = *(float4*)&xsT[k][ty * 4];
            float4 b0 = *(float4*)&ws[k][tx * 4];
            float4 b1 = *(float4*)&ws[k][64 + tx * 4];
            ull bb0 = pack2(b0.x, b0.y), bb1 = pack2(b0.z, b0.w);
            ull bb2 = pack2(b1.x, b1.y), bb3 = pack2(b1.z, b1.w);
            float ar[4] = {av.x, av.y, av.z, av.w};
#pragma unroll
            for (int r = 0; r < 4; r++) {
                ull arr = pack2(ar[r], ar[r]);
                fma2(acc[r][0], arr, bb0); fma2(acc[r][1], arr, bb1);
                fma2(acc[r][2], arr, bb2); fma2(acc[r][3], arr, bb3);
            }
        }
    }
#pragma unroll
    for (int r = 0; r < 4; r++) {
        float* dst = g_h + ((size_t)hd * NN + n0 + ty * 4 + r) * DOUT;
        float2 p0 = unpack2(acc[r][0]), p1 = unpack2(acc[r][1]);
        float2 p2 = unpack2(acc[r][2]), p3 = unpack2(acc[r][3]);
        *(float4*)(dst + tx * 4)      = make_float4(p0.x, p0.y, p1.x, p1.y);
        *(float4*)(dst + 64 + tx * 4) = make_float4(p2.x, p2.y, p3.x, p3.y);
    }
}

// ---------------------------------------------------------------------------
// K1b: transpose + bf16 hi/lo split:  g_h[hd][n][o] -> g_hThi/lo[hd][o][n]
// ---------------------------------------------------------------------------
__global__ __launch_bounds__(256) void k1b_t() {
    __shared__ float tile[128][129];
    const int hd = blockIdx.y, n0 = blockIdx.x * 128, tid = threadIdx.x;
    {
        int r = tid >> 1, ch = (tid & 1) * 64;
        const float* src = g_h + ((size_t)hd * NN + n0 + r) * DOUT + ch;
#pragma unroll
        for (int u = 0; u < 16; u++) {
            float4 v = *(const float4*)(src + u * 4);
            tile[r][ch + u * 4 + 0] = v.x; tile[r][ch + u * 4 + 1] = v.y;
            tile[r][ch + u * 4 + 2] = v.z; tile[r][ch + u * 4 + 3] = v.w;
        }
    }
    __syncthreads();
    {
        int o = tid >> 1, nh = (tid & 1) * 64;
        size_t obase = ((size_t)(hd * DOUT + o)) * NN + n0 + nh;
#pragma unroll
        for (int u = 0; u < 32; u++) {
            uint32_t lp;
            uint32_t hp = bf16x2_split_hi(tile[nh + 2 * u][o], tile[nh + 2 * u + 1][o], lp);
            *(uint32_t*)((char*)g_hThi + (obase + 2 * u) * 2) = hp;
            *(uint32_t*)((char*)g_hTlo + (obase + 2 * u) * 2) = lp;
        }
    }
}

// ---------------------------------------------------------------------------
// K2: scores + exp factorizations (unchanged)
// ---------------------------------------------------------------------------
__global__ __launch_bounds__(256) void k2_sef(const float* __restrict__ a) {
    const int warp = threadIdx.x >> 5, lane = threadIdx.x & 31;
    const int ridx = blockIdx.x * 8 + warp;
    const int hd = ridx >> 12;
    const float* hrow = g_h + (size_t)ridx * DOUT;
    const float* ah = a + hd * 256;
    float s1 = 0.f, s2 = 0.f;
#pragma unroll
    for (int c = lane; c < DOUT; c += 32) {
        float hv = hrow[c];
        s1 += hv * ah[c];
        s2 += hv * ah[DOUT + c];
    }
#pragma unroll
    for (int o = 16; o > 0; o >>= 1) {
        s1 += __shfl_xor_sync(0xffffffffu, s1, o);
        s2 += __shfl_xor_sync(0xffffffffu, s2, o);
    }
    if (lane == 0) {
        g_idat[ridx] = make_float4(s1, expf(s1), expf(0.2f * s1), 0.f);
        g_jdat[ridx] = make_float4(s2, expf(s2), expf(0.2f * s2), 0.f);
    }
}

// ---------------------------------------------------------------------------
// K3: HMMA (mma.sync bf16, hi/lo split) PV-GEMM with fused masked weights.
//   CTA: 128 i x 128 o x head. 8 warps; warp w owns i-rows [16w,16w+16).
//   smem layout (bytes):
//     [0]     zp   256 f  (1024)
//     [1024]  zi   128 f  (512)
//     [2048]  stage0:  whi 10240 | wlo 10240 | hhi 10240 | hlo 10240  (40960)
//     [43008] stage1:  same                                          (40960)
//   tiles are [128 rows][40 bf16] (RS=80B row stride), ldmatrix conflict-free.
// ---------------------------------------------------------------------------
#define K3_SMEM 83968

extern __shared__ char k3s[];
__global__ __launch_bounds__(256, 2) void k3_hmma(const int* __restrict__ A,
                                                  float* __restrict__ out) {
    const int hd = blockIdx.y, i0 = blockIdx.x * 128;
    const int tid = threadIdx.x, wid = tid >> 5, lane = tid & 31;
    const uint32_t sb = smem_u32(k3s);

    // --- build-phase identity
    const int il = tid >> 1, jh = tid & 1, ig = i0 + il;
    const float4 iv = g_idat[hd * NN + ig];
    const float si = iv.x, Ei = iv.y, Fi = iv.z;
    const int* Ar = A + (size_t)ig * NN;
    const float4* jd = g_jdat + hd * NN;
    // h staging identity (row o, which half of 32 j)
    const char* hsrc_hi = (const char*)g_hThi + ((size_t)(hd * DOUT + il)) * NN * 2;
    const char* hsrc_lo = (const char*)g_hTlo + ((size_t)(hd * DOUT + il)) * NN * 2;

    // --- compute-phase ldmatrix lane offsets
    const int aoff = wid * 16 * RS + (lane & 15) * RS + ((lane >> 4) * 8) * 2;
    const int boff = ((lane & 7) + ((lane >> 4) & 1) * 8) * RS + (((lane >> 3) & 1) * 8) * 2;

    float acc[16][4];
#pragma unroll
    for (int n = 0; n < 16; n++)
#pragma unroll
        for (int c = 0; c < 4; c++) acc[n][c] = 0.f;
    float zacc = 0.f;

    // ---------------- build tile t into stage s ----------------
    auto build = [&](int t) {
        const int s = t & 1;
        const int j0 = t * JT;
        char* wh = k3s + 2048 + s * 40960;
        char* wl = wh + 10240;
        char* hh = wh + 20480;
        char* hl = wh + 30720;
        // w tile: thread covers (row il, 16 j's)
        {
            const int jb = jh * 16;
            float z = 0.f;
#pragma unroll
            for (int q = 0; q < 16; q += 2) {
                const int j = j0 + jb + q;
                int2 av = *(const int2*)(Ar + j);
                float4 v0 = jd[j], v1 = jd[j + 1];
                float t0 = si + v0.x, t1 = si + v1.x;
                float w0 = (t0 >= 0.f) ? Ei * v0.y : Fi * v0.z;
                float w1 = (t1 >= 0.f) ? Ei * v1.y : Fi * v1.z;
                if (!((av.x > 0) || (j == ig)))     w0 = 0.f;
                if (!((av.y > 0) || (j + 1 == ig))) w1 = 0.f;
                z += w0 + w1;
                uint32_t lp;
                uint32_t hp = bf16x2_split_hi(w0, w1, lp);
                const uint32_t off = (uint32_t)il * RS + (jb + q) * 2;
                *(uint32_t*)(wh + off) = hp;
                *(uint32_t*)(wl + off) = lp;
            }
            zacc += z;
        }
        // h tile: thread copies 32B of row il (o), half jh
        {
            const uint32_t doff = (uint32_t)il * RS + jh * 32;
            const size_t sbyte = (size_t)(j0 + jh * 16) * 2;
            *(float4*)(hh + doff)      = *(const float4*)(hsrc_hi + sbyte);
            *(float4*)(hh + doff + 16) = *(const float4*)(hsrc_hi + sbyte + 16);
            *(float4*)(hl + doff)      = *(const float4*)(hsrc_lo + sbyte);
            *(float4*)(hl + doff + 16) = *(const float4*)(hsrc_lo + sbyte + 16);
        }
    };

    // ---------------- compute tile t from stage s ----------------
    auto compute = [&](int t) {
        const int s = t & 1;
        const uint32_t wbase = sb + 2048 + s * 40960;
        const uint32_t hbase = wbase + 20480;
#pragma unroll
        for (int kk = 0; kk < 2; kk++) {           // two k16 steps
            const uint32_t kb = kk * 32;           // 16 bf16 = 32 bytes
            uint32_t ahi[4], alo[4];
            ldsm4(ahi, wbase + aoff + kb);
            ldsm4(alo, wbase + 10240 + aoff + kb);
#pragma unroll
            for (int nb = 0; nb < 8; nb++) {
                uint32_t bhi[4], blo[4];
                const uint32_t hb = hbase + nb * 16 * RS + boff + kb;
                ldsm4(bhi, hb);
                ldsm4(blo, hb + 10240);
                mma_bf16(acc[2 * nb],     ahi, bhi[0], bhi[1]);
                mma_bf16(acc[2 * nb],     ahi, blo[0], blo[1]);
                mma_bf16(acc[2 * nb],     alo, bhi[0], bhi[1]);
                mma_bf16(acc[2 * nb + 1], ahi, bhi[2], bhi[3]);
                mma_bf16(acc[2 * nb + 1], ahi, blo[2], blo[3]);
                mma_bf16(acc[2 * nb + 1], alo, bhi[2], bhi[3]);
            }
        }
    };

    build(0);
    __syncthreads();
    for (int t = 0; t < NN / JT; t++) {
        compute(t);
        if (t + 1 < NN / JT) build(t + 1);
        __syncthreads();
    }

    // ---- Z reduction
    float* zp = (float*)(k3s);
    float* zi = (float*)(k3s + 1024);
    zp[tid] = zacc;
    __syncthreads();
    if (tid < 128) zi[tid] = 1.0f / (zp[2 * tid] + zp[2 * tid + 1]);
    __syncthreads();

    // ---- epilogue: normalize + store
    const int r0 = wid * 16 + (lane >> 2), r1 = r0 + 8;
    const float s0 = zi[r0], s1 = zi[r1];
    float* o0 = out + (size_t)(i0 + r0) * (NH * DOUT) + hd * DOUT + (lane & 3) * 2;
    float* o1 = out + (size_t)(i0 + r1) * (NH * DOUT) + hd * DOUT + (lane & 3) * 2;
#pragma unroll
    for (int nt = 0; nt < 16; nt++) {
        *(float2*)(o0 + nt * 8) = make_float2(acc[nt][0] * s0, acc[nt][1] * s0);
        *(float2*)(o1 + nt * 8) = make_float2(acc[nt][2] * s1, acc[nt][3] * s1);
    }
}

// ---------------------------------------------------------------------------
extern "C" void kernel_launch(void* const* d_in, const int* in_sizes, int n_in,
                              void* d_out, int out_size) {
    const float* x = (const float*)d_in[0];   // (4096, 256) f32
    const int*   A = (const int*)d_in[1];     // (4096, 4096) i32
    const float* W = (const float*)d_in[2];   // (4, 256, 128) f32
    const float* a = (const float*)d_in[3];   // (4, 256, 1) f32
    float* out = (float*)d_out;               // (4096, 512) f32

    cudaFuncSetAttribute(k3_hmma, cudaFuncAttributeMaxDynamicSharedMemorySize, K3_SMEM);

    k1_gemm_h<<<dim3(NN / 64, NH), 256>>>(x, W);
    k1b_t<<<dim3(NN / 128, NH), 256>>>();
    k2_sef<<<(NH * NN) / 8, 256>>>(a);
    k3_hmma<<<dim3(NN / 128, NH), 256, K3_SMEM>>>(A, out);
}